// round 5
// baseline (speedup 1.0000x reference)
#include <cuda_runtime.h>
#include <cuda_fp16.h>
#include <cstdint>
#include <cstddef>

// ============================================================================
// Problem constants
// ============================================================================
#define B_ROWS 8192
#define K_DIM  4096
#define N_DIM  4096          // 8 experts * 512

#define MT 128               // CTA M tile
#define NT 128               // CTA N tile
#define BK 64                // K per pipeline chunk
#define NCHUNK (K_DIM / BK)  // 64
#define MTILES (B_ROWS / MT) // 64
#define NTILES (N_DIM / NT)  // 32

#define A_TILE_BYTES (128 * 128)  // 16384: 128 rows x 64 fp16 (128B/row)
#define W_TILE_BYTES (256 * 128)  // 32768: W stored as 256-row tiles in scratch

// smem stage: Ah, Al, Bh, Bl each 16KB; 3 stages
#define OFF_AH 0
#define OFF_AL 16384
#define OFF_BH 32768
#define OFF_BL 49152
#define STAGE_BYTES 65536
#define NSTAGE 3
#define SMEM_TOTAL (NSTAGE * STAGE_BYTES)   // 196608

// ============================================================================
// Static device scratch: pre-split fp16, pre-tiled, XOR-swizzled
// ============================================================================
__device__ uint4 g_xh[(size_t)B_ROWS * K_DIM / 8];  // 64 MB
__device__ uint4 g_xl[(size_t)B_ROWS * K_DIM / 8];  // 64 MB
__device__ uint4 g_wh[(size_t)N_DIM * K_DIM / 8];   // 32 MB
__device__ uint4 g_wl[(size_t)N_DIM * K_DIM / 8];   // 32 MB

// ============================================================================
// PTX helpers (base-sm_100-safe)
// ============================================================================
__device__ __forceinline__ uint32_t smem_u32(const void* p) {
    uint32_t a;
    asm("{ .reg .u64 t; cvta.to.shared.u64 t, %1; cvt.u32.u64 %0, t; }" : "=r"(a) : "l"(p));
    return a;
}

__device__ __forceinline__ void cp16(uint32_t dst, const void* src) {
    asm volatile("cp.async.cg.shared.global [%0], [%1], 16;" :: "r"(dst), "l"(src) : "memory");
}
#define CP_COMMIT() asm volatile("cp.async.commit_group;" ::: "memory")
#define CP_WAIT1()  asm volatile("cp.async.wait_group 1;" ::: "memory")

#define LDSM4(r0, r1, r2, r3, addr) \
    asm volatile("ldmatrix.sync.aligned.m8n8.x4.shared.b16 {%0,%1,%2,%3}, [%4];" \
        : "=r"(r0), "=r"(r1), "=r"(r2), "=r"(r3) : "r"(addr))

#define MMA16816(c, a, b0, b1) \
    asm volatile("mma.sync.aligned.m16n8k16.row.col.f32.f16.f16.f32 " \
        "{%0,%1,%2,%3}, {%4,%5,%6,%7}, {%8,%9}, {%0,%1,%2,%3};" \
        : "+f"((c)[0]), "+f"((c)[1]), "+f"((c)[2]), "+f"((c)[3]) \
        : "r"((a)[0]), "r"((a)[1]), "r"((a)[2]), "r"((a)[3]), "r"(b0), "r"(b1))

__device__ __forceinline__ float fast_tanh(float x) {
    float e = __expf(2.0f * x);
    return 1.0f - 2.0f / (e + 1.0f);
}

// ============================================================================
// Split fp32 -> fp16 (hi, lo), pre-tiled XOR-swizzled layout.
// which: 0 -> x (row tiles of 128), 1 -> W (row tiles of 256)
// ============================================================================
__global__ void split_kernel(const float* __restrict__ src, int total, int rshift,
                             int tile_u4, int which) {
    int gid = blockIdx.x * blockDim.x + threadIdx.x;
    if (gid >= total) return;
    uint4* __restrict__ dh = which ? g_wh : g_xh;
    uint4* __restrict__ dl = which ? g_wl : g_xl;

    int row = gid >> 9;
    int g   = gid & 511;
    int col = g << 3;
    int chunk = col >> 6;
    int lc    = col & 63;
    int tile  = ((row >> rshift) << 6) + chunk;
    int lr    = row & ((1 << rshift) - 1);
    uint32_t byte_off = (uint32_t)lr * 128u + (uint32_t)lc * 2u;
    uint32_t sw = byte_off ^ ((byte_off >> 3) & 0x70);
    size_t idx = (size_t)tile * (size_t)tile_u4 + (sw >> 4);

    const float4* s4 = (const float4*)(src + (size_t)row * K_DIM + col);
    float4 a = s4[0], b = s4[1];
    float v[8] = {a.x, a.y, a.z, a.w, b.x, b.y, b.z, b.w};
    uint32_t ph[4], pl[4];
#pragma unroll
    for (int j = 0; j < 4; j++) {
        __half h0 = __float2half_rn(v[2*j]);
        __half h1 = __float2half_rn(v[2*j+1]);
        __half l0 = __float2half_rn(v[2*j]   - __half2float(h0));
        __half l1 = __float2half_rn(v[2*j+1] - __half2float(h1));
        __half2 hh = __halves2half2(h0, h1);
        __half2 ll = __halves2half2(l0, l1);
        ph[j] = *reinterpret_cast<uint32_t*>(&hh);
        pl[j] = *reinterpret_cast<uint32_t*>(&ll);
    }
    dh[idx] = make_uint4(ph[0], ph[1], ph[2], ph[3]);
    dl[idx] = make_uint4(pl[0], pl[1], pl[2], pl[3]);
}

// ============================================================================
// Gate: logits = x @ gate_w^T + gate_b + ttm; softmax over 8 experts.
// ============================================================================
__global__ void gate_kernel(const float* __restrict__ x, const float* __restrict__ gw,
                            const float* __restrict__ gb, const float* __restrict__ ttm,
                            float* __restrict__ wout) {
    __shared__ float s_gw[8][512];
    __shared__ float s_gb[8], s_ttm[8];
    int wid = threadIdx.x >> 5, lane = threadIdx.x & 31;
    int row = blockIdx.x * 8 + wid;
    if (threadIdx.x < 8) { s_gb[threadIdx.x] = gb[threadIdx.x]; s_ttm[threadIdx.x] = ttm[threadIdx.x]; }

    float acc[8];
#pragma unroll
    for (int e = 0; e < 8; e++) acc[e] = 0.f;

    for (int kb = 0; kb < K_DIM; kb += 512) {
        __syncthreads();
        for (int i = threadIdx.x; i < 8 * 512; i += 256) {
            int e = i >> 9, k = i & 511;
            s_gw[e][k] = gw[(size_t)e * K_DIM + kb + k];
        }
        __syncthreads();
        for (int k = lane; k < 512; k += 32) {
            float xv = __ldg(x + (size_t)row * K_DIM + kb + k);
#pragma unroll
            for (int e = 0; e < 8; e++) acc[e] += xv * s_gw[e][k];
        }
    }
#pragma unroll
    for (int off = 16; off; off >>= 1)
#pragma unroll
        for (int e = 0; e < 8; e++) acc[e] += __shfl_down_sync(0xFFFFFFFFu, acc[e], off);

    if (lane == 0) {
        float lg[8], mx = -1e30f;
#pragma unroll
        for (int e = 0; e < 8; e++) { lg[e] = acc[e] + s_gb[e] + s_ttm[e]; mx = fmaxf(mx, lg[e]); }
        float s = 0.f;
#pragma unroll
        for (int e = 0; e < 8; e++) { lg[e] = expf(lg[e] - mx); s += lg[e]; }
        float inv = 1.0f / s;
#pragma unroll
        for (int e = 0; e < 8; e++) wout[(size_t)row * 8 + e] = lg[e] * inv;
    }
}

// ============================================================================
// GEMM: out = tanh( X @ Wflat^T ), fp16x3 via mma.sync m16n8k16, fp32 accum.
// 256 threads, 8 warps (2m x 4n), tile 128x128, BK=64, 3-stage cp.async,
// single sync per chunk, term-outer MMA ordering (16-MMA accumulator reuse
// distance -> HMMA RAW chains fully hidden).
// ============================================================================
__global__ void __launch_bounds__(256, 1) gemm_kernel(float* __restrict__ out) {
    extern __shared__ __align__(1024) char smem[];
    const uint32_t sb = smem_u32(smem);
    const int tid = threadIdx.x;
    const int wid = tid >> 5, lane = tid & 31;
    const int warp_m = wid & 1;        // 0..1 (64 rows)
    const int warp_n = wid >> 1;       // 0..3 (32 cols)

    const int bid = blockIdx.x;
    const int ntile = bid & 31;
    const int mtile = bid >> 5;

    const char* axh = (const char*)g_xh + (size_t)mtile * NCHUNK * A_TILE_BYTES;
    const char* axl = (const char*)g_xl + (size_t)mtile * NCHUNK * A_TILE_BYTES;
    const int wtile = ntile >> 1, whalf = ntile & 1;
    const char* bwh = (const char*)g_wh + (size_t)wtile * NCHUNK * W_TILE_BYTES + (size_t)whalf * 16384;
    const char* bwl = (const char*)g_wl + (size_t)wtile * NCHUNK * W_TILE_BYTES + (size_t)whalf * 16384;

    const uint32_t cpo = (uint32_t)tid * 16u;

    // ldmatrix per-lane address constants
    const int a_moff = (((lane >> 3) & 1) << 3) + (lane & 7);
    const int a_kb   = (lane >> 4) << 4;
    const int a_row  = warp_m * 64 + a_moff;
    const uint32_t a_mask = (uint32_t)((a_row & 7) << 4);
    const uint32_t a_rowb = (uint32_t)a_row * 128u;
    const int b_noff = ((lane >> 4) << 3) + (lane & 7);
    const int b_kb   = ((lane >> 3) & 1) << 4;
    const int b_row  = warp_n * 32 + b_noff;
    const uint32_t b_mask = (uint32_t)((b_row & 7) << 4);
    const uint32_t b_rowb = (uint32_t)b_row * 128u;

    uint32_t akt[4], bkt[4];
#pragma unroll
    for (int ks = 0; ks < 4; ks++) {
        akt[ks] = ((uint32_t)(ks * 32 + a_kb)) ^ a_mask;
        bkt[ks] = ((uint32_t)(ks * 32 + b_kb)) ^ b_mask;
    }

    float acc[4][4][4];
#pragma unroll
    for (int mi = 0; mi < 4; mi++)
#pragma unroll
        for (int ni = 0; ni < 4; ni++)
#pragma unroll
            for (int r = 0; r < 4; r++) acc[mi][ni][r] = 0.f;

#define LOAD_STAGE(stage, c) do {                                              \
        uint32_t d = sb + (uint32_t)(stage) * STAGE_BYTES + cpo;               \
        const char* s0 = axh + (size_t)(c) * A_TILE_BYTES;                     \
        const char* s1 = axl + (size_t)(c) * A_TILE_BYTES;                     \
        const char* s2 = bwh + (size_t)(c) * W_TILE_BYTES;                     \
        const char* s3 = bwl + (size_t)(c) * W_TILE_BYTES;                     \
        _Pragma("unroll")                                                      \
        for (int i = 0; i < 4; i++) {                                          \
            cp16(d + OFF_AH + i * 4096u, s0 + cpo + i * 4096);                 \
            cp16(d + OFF_AL + i * 4096u, s1 + cpo + i * 4096);                 \
            cp16(d + OFF_BH + i * 4096u, s2 + cpo + i * 4096);                 \
            cp16(d + OFF_BL + i * 4096u, s3 + cpo + i * 4096);                 \
        }                                                                      \
    } while (0)

    LOAD_STAGE(0, 0); CP_COMMIT();
    LOAD_STAGE(1, 1); CP_COMMIT();

    int stage = 0;
    for (int c = 0; c < NCHUNK; c++) {
        CP_WAIT1();                 // chunk c resident (<=1 younger group pending)
        __syncthreads();            // all warps past compute of c-1 (its stage is the prefetch target)

        // prefetch chunk c+2 BEFORE compute; target stage (c+2)%3 != current read stage c%3
        if (c + 2 < NCHUNK) {
            int ps = stage + 2; if (ps >= NSTAGE) ps -= NSTAGE;
            LOAD_STAGE(ps, c + 2);
        }
        CP_COMMIT();

        const uint32_t stg = sb + (uint32_t)stage * STAGE_BYTES;
        const uint32_t aH = stg + OFF_AH + a_rowb;
        const uint32_t aL = stg + OFF_AL + a_rowb;
        const uint32_t bH = stg + OFF_BH + b_rowb;
        const uint32_t bL = stg + OFF_BL + b_rowb;

#pragma unroll
        for (int ks = 0; ks < 4; ks++) {
            uint32_t ah[4][4], al[4][4], bh[4][2], bl[4][2];
#pragma unroll
            for (int mi = 0; mi < 4; mi++) {
                LDSM4(ah[mi][0], ah[mi][1], ah[mi][2], ah[mi][3], aH + mi * 2048u + akt[ks]);
                LDSM4(al[mi][0], al[mi][1], al[mi][2], al[mi][3], aL + mi * 2048u + akt[ks]);
            }
#pragma unroll
            for (int p = 0; p < 2; p++) {
                LDSM4(bh[2*p][0], bh[2*p][1], bh[2*p+1][0], bh[2*p+1][1], bH + p * 2048u + bkt[ks]);
                LDSM4(bl[2*p][0], bl[2*p][1], bl[2*p+1][0], bl[2*p+1][1], bL + p * 2048u + bkt[ks]);
            }
            // term-outer ordering: accumulator reuse distance = 16 MMAs
#pragma unroll
            for (int mi = 0; mi < 4; mi++)
#pragma unroll
                for (int ni = 0; ni < 4; ni++)
                    MMA16816(acc[mi][ni], ah[mi], bh[ni][0], bh[ni][1]);
#pragma unroll
            for (int mi = 0; mi < 4; mi++)
#pragma unroll
                for (int ni = 0; ni < 4; ni++)
                    MMA16816(acc[mi][ni], ah[mi], bl[ni][0], bl[ni][1]);
#pragma unroll
            for (int mi = 0; mi < 4; mi++)
#pragma unroll
                for (int ni = 0; ni < 4; ni++)
                    MMA16816(acc[mi][ni], al[mi], bh[ni][0], bh[ni][1]);
        }
        if (++stage >= NSTAGE) stage = 0;
    }

    // ---- epilogue: tanh + float2 stores ----
    const int row0 = mtile * 128 + warp_m * 64 + (lane >> 2);
    const int col0 = ntile * 128 + warp_n * 32 + (lane & 3) * 2;
#pragma unroll
    for (int mi = 0; mi < 4; mi++) {
#pragma unroll
        for (int ni = 0; ni < 4; ni++) {
            float* p0 = out + (size_t)(row0 + mi * 16) * N_DIM + col0 + ni * 8;
            float* p1 = p0 + 8 * N_DIM;
            float2 v0, v1;
            v0.x = fast_tanh(acc[mi][ni][0]); v0.y = fast_tanh(acc[mi][ni][1]);
            v1.x = fast_tanh(acc[mi][ni][2]); v1.y = fast_tanh(acc[mi][ni][3]);
            *reinterpret_cast<float2*>(p0) = v0;
            *reinterpret_cast<float2*>(p1) = v1;
        }
    }
#undef LOAD_STAGE
}

// ============================================================================
// Launch
// ============================================================================
extern "C" void kernel_launch(void* const* d_in, const int* in_sizes, int n_in,
                              void* d_out, int out_size) {
    const float* x   = (const float*)d_in[0];
    const float* W   = (const float*)d_in[1];
    const float* gw  = (const float*)d_in[2];
    const float* gb  = (const float*)d_in[3];
    const float* ttm = (const float*)d_in[4];
    float* out  = (float*)d_out;
    float* wout = out + (size_t)B_ROWS * N_DIM;

    cudaFuncSetAttribute(gemm_kernel, cudaFuncAttributeMaxDynamicSharedMemorySize, SMEM_TOTAL);

    {   // split x: row tiles of 128 (rshift 7), tile = 16384B = 1024 uint4
        int total = B_ROWS * 512;
        split_kernel<<<(total + 255) / 256, 256>>>(x, total, 7, 1024, 0);
    }
    {   // split W: row tiles of 256 (rshift 8), tile = 32768B = 2048 uint4
        int total = N_DIM * 512;
        split_kernel<<<(total + 255) / 256, 256>>>(W, total, 8, 2048, 1);
    }
    gate_kernel<<<B_ROWS / 8, 256>>>(x, gw, gb, ttm, wout);
    gemm_kernel<<<MTILES * NTILES, 256, SMEM_TOTAL>>>(out);
}

// round 6
// speedup vs baseline: 1.0635x; 1.0635x over previous
#include <cuda_runtime.h>
#include <cuda_fp16.h>
#include <cstdint>
#include <cstddef>

// ============================================================================
// Problem constants
// ============================================================================
#define B_ROWS 8192
#define K_DIM  4096
#define N_DIM  4096          // 8 experts * 512

#define MT 128               // CTA M tile
#define NT 256               // CTA N tile
#define BK 64                // K per pipeline chunk
#define NCHUNK (K_DIM / BK)  // 64
#define MTILES (B_ROWS / MT) // 64
#define NTILES (N_DIM / NT)  // 16

#define A_TILE_BYTES (128 * 128)  // 16384: 128 rows x 64 fp16 (128B/row)
#define W_TILE_BYTES (256 * 128)  // 32768: W stored as 256-row tiles

// smem stage: Ah 16K, Al 16K, Bh 32K, Bl 32K = 96KB; 2 stages
#define OFF_AH 0
#define OFF_AL 16384
#define OFF_BH 32768
#define OFF_BL 65536
#define STAGE_BYTES 98304
#define SMEM_TOTAL (2 * STAGE_BYTES)   // 196608

// ============================================================================
// Static device scratch: pre-split fp16, pre-tiled, XOR-swizzled
// ============================================================================
__device__ uint4 g_xh[(size_t)B_ROWS * K_DIM / 8];  // 64 MB
__device__ uint4 g_xl[(size_t)B_ROWS * K_DIM / 8];  // 64 MB
__device__ uint4 g_wh[(size_t)N_DIM * K_DIM / 8];   // 32 MB
__device__ uint4 g_wl[(size_t)N_DIM * K_DIM / 8];   // 32 MB

// ============================================================================
// PTX helpers (base-sm_100-safe)
// ============================================================================
__device__ __forceinline__ uint32_t smem_u32(const void* p) {
    uint32_t a;
    asm("{ .reg .u64 t; cvta.to.shared.u64 t, %1; cvt.u32.u64 %0, t; }" : "=r"(a) : "l"(p));
    return a;
}

__device__ __forceinline__ void cp16(uint32_t dst, const void* src) {
    asm volatile("cp.async.cg.shared.global [%0], [%1], 16;" :: "r"(dst), "l"(src) : "memory");
}
#define CP_COMMIT() asm volatile("cp.async.commit_group;" ::: "memory")
#define CP_WAIT1()  asm volatile("cp.async.wait_group 1;" ::: "memory")

#define LDSM4(r0, r1, r2, r3, addr) \
    asm volatile("ldmatrix.sync.aligned.m8n8.x4.shared.b16 {%0,%1,%2,%3}, [%4];" \
        : "=r"(r0), "=r"(r1), "=r"(r2), "=r"(r3) : "r"(addr))

#define MMA16816(c, a, b0, b1) \
    asm volatile("mma.sync.aligned.m16n8k16.row.col.f32.f16.f16.f32 " \
        "{%0,%1,%2,%3}, {%4,%5,%6,%7}, {%8,%9}, {%0,%1,%2,%3};" \
        : "+f"((c)[0]), "+f"((c)[1]), "+f"((c)[2]), "+f"((c)[3]) \
        : "r"((a)[0]), "r"((a)[1]), "r"((a)[2]), "r"((a)[3]), "r"(b0), "r"(b1))

__device__ __forceinline__ float fast_tanh(float x) {
    float e = __expf(2.0f * x);
    return 1.0f - 2.0f / (e + 1.0f);
}

// ============================================================================
// Split fp32 -> fp16 (hi, lo), pre-tiled XOR-swizzled layout.
// which: 0 -> x (row tiles of 128), 1 -> W (row tiles of 256)
// ============================================================================
__global__ void split_kernel(const float* __restrict__ src, int total, int rshift,
                             int tile_u4, int which) {
    int gid = blockIdx.x * blockDim.x + threadIdx.x;
    if (gid >= total) return;
    uint4* __restrict__ dh = which ? g_wh : g_xh;
    uint4* __restrict__ dl = which ? g_wl : g_xl;

    int row = gid >> 9;
    int g   = gid & 511;
    int col = g << 3;
    int chunk = col >> 6;
    int lc    = col & 63;
    int tile  = ((row >> rshift) << 6) + chunk;
    int lr    = row & ((1 << rshift) - 1);
    uint32_t byte_off = (uint32_t)lr * 128u + (uint32_t)lc * 2u;
    uint32_t sw = byte_off ^ ((byte_off >> 3) & 0x70);
    size_t idx = (size_t)tile * (size_t)tile_u4 + (sw >> 4);

    const float4* s4 = (const float4*)(src + (size_t)row * K_DIM + col);
    float4 a = s4[0], b = s4[1];
    float v[8] = {a.x, a.y, a.z, a.w, b.x, b.y, b.z, b.w};
    uint32_t ph[4], pl[4];
#pragma unroll
    for (int j = 0; j < 4; j++) {
        __half h0 = __float2half_rn(v[2*j]);
        __half h1 = __float2half_rn(v[2*j+1]);
        __half l0 = __float2half_rn(v[2*j]   - __half2float(h0));
        __half l1 = __float2half_rn(v[2*j+1] - __half2float(h1));
        __half2 hh = __halves2half2(h0, h1);
        __half2 ll = __halves2half2(l0, l1);
        ph[j] = *reinterpret_cast<uint32_t*>(&hh);
        pl[j] = *reinterpret_cast<uint32_t*>(&ll);
    }
    dh[idx] = make_uint4(ph[0], ph[1], ph[2], ph[3]);
    dl[idx] = make_uint4(pl[0], pl[1], pl[2], pl[3]);
}

// ============================================================================
// Gate: logits = x @ gate_w^T + gate_b + ttm; softmax over 8 experts.
// ============================================================================
__global__ void gate_kernel(const float* __restrict__ x, const float* __restrict__ gw,
                            const float* __restrict__ gb, const float* __restrict__ ttm,
                            float* __restrict__ wout) {
    __shared__ float s_gw[8][512];
    __shared__ float s_gb[8], s_ttm[8];
    int wid = threadIdx.x >> 5, lane = threadIdx.x & 31;
    int row = blockIdx.x * 8 + wid;
    if (threadIdx.x < 8) { s_gb[threadIdx.x] = gb[threadIdx.x]; s_ttm[threadIdx.x] = ttm[threadIdx.x]; }

    float acc[8];
#pragma unroll
    for (int e = 0; e < 8; e++) acc[e] = 0.f;

    for (int kb = 0; kb < K_DIM; kb += 512) {
        __syncthreads();
        for (int i = threadIdx.x; i < 8 * 512; i += 256) {
            int e = i >> 9, k = i & 511;
            s_gw[e][k] = gw[(size_t)e * K_DIM + kb + k];
        }
        __syncthreads();
        for (int k = lane; k < 512; k += 32) {
            float xv = __ldg(x + (size_t)row * K_DIM + kb + k);
#pragma unroll
            for (int e = 0; e < 8; e++) acc[e] += xv * s_gw[e][k];
        }
    }
#pragma unroll
    for (int off = 16; off; off >>= 1)
#pragma unroll
        for (int e = 0; e < 8; e++) acc[e] += __shfl_down_sync(0xFFFFFFFFu, acc[e], off);

    if (lane == 0) {
        float lg[8], mx = -1e30f;
#pragma unroll
        for (int e = 0; e < 8; e++) { lg[e] = acc[e] + s_gb[e] + s_ttm[e]; mx = fmaxf(mx, lg[e]); }
        float s = 0.f;
#pragma unroll
        for (int e = 0; e < 8; e++) { lg[e] = expf(lg[e] - mx); s += lg[e]; }
        float inv = 1.0f / s;
#pragma unroll
        for (int e = 0; e < 8; e++) wout[(size_t)row * 8 + e] = lg[e] * inv;
    }
}

// ============================================================================
// GEMM: out = tanh( X @ Wflat^T ), fp16x3 via mma.sync m16n8k16, fp32 accum.
// 256 threads, 8 warps (2m x 4n), CTA tile 128x256, warp tile 64x64, BK=64,
// 2-stage cp.async. 64x64 warp tile raises MMA/LDSM ratio 4->6 so the smem
// crossbar (the R4-measured binding constraint) drops below the HMMA floor.
// ============================================================================
__global__ void __launch_bounds__(256, 1) gemm_kernel(float* __restrict__ out) {
    extern __shared__ __align__(1024) char smem[];
    const uint32_t sb = smem_u32(smem);
    const int tid = threadIdx.x;
    const int wid = tid >> 5, lane = tid & 31;
    const int warp_m = wid & 1;        // 0..1 (64 rows)
    const int warp_n = wid >> 1;       // 0..3 (64 cols)

    const int bid = blockIdx.x;
    const int ntile = bid & 15;
    const int mtile = bid >> 4;

    const char* axh = (const char*)g_xh + (size_t)mtile * NCHUNK * A_TILE_BYTES;
    const char* axl = (const char*)g_xl + (size_t)mtile * NCHUNK * A_TILE_BYTES;
    const char* bwh = (const char*)g_wh + (size_t)ntile * NCHUNK * W_TILE_BYTES;
    const char* bwl = (const char*)g_wl + (size_t)ntile * NCHUNK * W_TILE_BYTES;

    const uint32_t cpo = (uint32_t)tid * 16u;

    // ldmatrix per-lane address constants
    const int a_moff = (((lane >> 3) & 1) << 3) + (lane & 7);
    const int a_kb   = (lane >> 4) << 4;
    const int a_row  = warp_m * 64 + a_moff;              // +16 per mi
    const uint32_t a_mask = (uint32_t)((a_row & 7) << 4);
    const uint32_t a_rowb = (uint32_t)a_row * 128u;
    const int b_noff = ((lane >> 4) << 3) + (lane & 7);
    const int b_kb   = ((lane >> 3) & 1) << 4;
    const int b_row  = warp_n * 64 + b_noff;              // +16 per p
    const uint32_t b_mask = (uint32_t)((b_row & 7) << 4);
    const uint32_t b_rowb = (uint32_t)b_row * 128u;

    uint32_t akt[4], bkt[4];
#pragma unroll
    for (int ks = 0; ks < 4; ks++) {
        akt[ks] = ((uint32_t)(ks * 32 + a_kb)) ^ a_mask;
        bkt[ks] = ((uint32_t)(ks * 32 + b_kb)) ^ b_mask;
    }

    float acc[4][8][4];
#pragma unroll
    for (int mi = 0; mi < 4; mi++)
#pragma unroll
        for (int ni = 0; ni < 8; ni++)
#pragma unroll
            for (int r = 0; r < 4; r++) acc[mi][ni][r] = 0.f;

#define LOAD_STAGE(stage, c) do {                                              \
        uint32_t d = sb + (uint32_t)(stage) * STAGE_BYTES + cpo;               \
        const char* s0 = axh + (size_t)(c) * A_TILE_BYTES;                     \
        const char* s1 = axl + (size_t)(c) * A_TILE_BYTES;                     \
        const char* s2 = bwh + (size_t)(c) * W_TILE_BYTES;                     \
        const char* s3 = bwl + (size_t)(c) * W_TILE_BYTES;                     \
        _Pragma("unroll")                                                      \
        for (int i = 0; i < 4; i++) {                                          \
            cp16(d + OFF_AH + i * 4096u, s0 + cpo + i * 4096);                 \
            cp16(d + OFF_AL + i * 4096u, s1 + cpo + i * 4096);                 \
        }                                                                      \
        _Pragma("unroll")                                                      \
        for (int i = 0; i < 8; i++) {                                          \
            cp16(d + OFF_BH + i * 4096u, s2 + cpo + i * 4096);                 \
            cp16(d + OFF_BL + i * 4096u, s3 + cpo + i * 4096);                 \
        }                                                                      \
    } while (0)

    LOAD_STAGE(0, 0); CP_COMMIT();
    LOAD_STAGE(1, 1); CP_COMMIT();

    for (int c = 0; c < NCHUNK; c++) {
        CP_WAIT1();
        __syncthreads();
        const uint32_t stg = sb + (uint32_t)(c & 1) * STAGE_BYTES;
        const uint32_t aH = stg + OFF_AH + a_rowb;
        const uint32_t aL = stg + OFF_AL + a_rowb;
        const uint32_t bH = stg + OFF_BH + b_rowb;
        const uint32_t bL = stg + OFF_BL + b_rowb;

#pragma unroll
        for (int ks = 0; ks < 4; ks++) {
            uint32_t ah[4][4], bh[8][2];
#pragma unroll
            for (int mi = 0; mi < 4; mi++)
                LDSM4(ah[mi][0], ah[mi][1], ah[mi][2], ah[mi][3], aH + mi * 2048u + akt[ks]);
#pragma unroll
            for (int p = 0; p < 4; p++)
                LDSM4(bh[2*p][0], bh[2*p][1], bh[2*p+1][0], bh[2*p+1][1], bH + p * 2048u + bkt[ks]);

            // term hh
#pragma unroll
            for (int mi = 0; mi < 4; mi++)
#pragma unroll
                for (int ni = 0; ni < 8; ni++)
                    MMA16816(acc[mi][ni], ah[mi], bh[ni][0], bh[ni][1]);

            // term lh: load al (reuses nothing of bh; ah stays live for hl)
            {
                uint32_t al[4][4];
#pragma unroll
                for (int mi = 0; mi < 4; mi++)
                    LDSM4(al[mi][0], al[mi][1], al[mi][2], al[mi][3], aL + mi * 2048u + akt[ks]);
#pragma unroll
                for (int mi = 0; mi < 4; mi++)
#pragma unroll
                    for (int ni = 0; ni < 8; ni++)
                        MMA16816(acc[mi][ni], al[mi], bh[ni][0], bh[ni][1]);
            }

            // term hl: bl reuses al/bh register space
            {
                uint32_t bl[8][2];
#pragma unroll
                for (int p = 0; p < 4; p++)
                    LDSM4(bl[2*p][0], bl[2*p][1], bl[2*p+1][0], bl[2*p+1][1], bL + p * 2048u + bkt[ks]);
#pragma unroll
                for (int mi = 0; mi < 4; mi++)
#pragma unroll
                    for (int ni = 0; ni < 8; ni++)
                        MMA16816(acc[mi][ni], ah[mi], bl[ni][0], bl[ni][1]);
            }
        }
        __syncthreads();
        if (c + 2 < NCHUNK) { LOAD_STAGE(c & 1, c + 2); }
        CP_COMMIT();
    }

    // ---- epilogue: tanh + float2 stores ----
    const int row0 = mtile * 128 + warp_m * 64 + (lane >> 2);
    const int col0 = ntile * 256 + warp_n * 64 + (lane & 3) * 2;
#pragma unroll
    for (int mi = 0; mi < 4; mi++) {
#pragma unroll
        for (int ni = 0; ni < 8; ni++) {
            float* p0 = out + (size_t)(row0 + mi * 16) * N_DIM + col0 + ni * 8;
            float* p1 = p0 + 8 * N_DIM;
            float2 v0, v1;
            v0.x = fast_tanh(acc[mi][ni][0]); v0.y = fast_tanh(acc[mi][ni][1]);
            v1.x = fast_tanh(acc[mi][ni][2]); v1.y = fast_tanh(acc[mi][ni][3]);
            *reinterpret_cast<float2*>(p0) = v0;
            *reinterpret_cast<float2*>(p1) = v1;
        }
    }
#undef LOAD_STAGE
}

// ============================================================================
// Launch
// ============================================================================
extern "C" void kernel_launch(void* const* d_in, const int* in_sizes, int n_in,
                              void* d_out, int out_size) {
    const float* x   = (const float*)d_in[0];
    const float* W   = (const float*)d_in[1];
    const float* gw  = (const float*)d_in[2];
    const float* gb  = (const float*)d_in[3];
    const float* ttm = (const float*)d_in[4];
    float* out  = (float*)d_out;
    float* wout = out + (size_t)B_ROWS * N_DIM;

    cudaFuncSetAttribute(gemm_kernel, cudaFuncAttributeMaxDynamicSharedMemorySize, SMEM_TOTAL);

    {   // split x: row tiles of 128 (rshift 7), tile = 16384B = 1024 uint4
        int total = B_ROWS * 512;
        split_kernel<<<(total + 255) / 256, 256>>>(x, total, 7, 1024, 0);
    }
    {   // split W: row tiles of 256 (rshift 8), tile = 32768B = 2048 uint4
        int total = N_DIM * 512;
        split_kernel<<<(total + 255) / 256, 256>>>(W, total, 8, 2048, 1);
    }
    gate_kernel<<<B_ROWS / 8, 256>>>(x, gw, gb, ttm, wout);
    gemm_kernel<<<MTILES * NTILES, 256, SMEM_TOTAL>>>(out);
}